// round 3
// baseline (speedup 1.0000x reference)
#include <cuda_runtime.h>
#include <cuda_bf16.h>

// Hierarchy: 8 leaf groups (children of nodes 65..72); nodes 65..68 under 73,
// 69..72 under 74; root 75.
// Fused output layout (flat): [ leaf_path_probs (N*65) | node_probs (N*76) ]

__constant__ int   c_ga[8]  = {0, 7, 30, 48, 53, 58, 59, 62};
__constant__ int   c_gb[8]  = {7, 30, 48, 53, 58, 59, 62, 65};
__constant__ float c_gsz[8] = {7.f, 23.f, 18.f, 5.f, 5.f, 1.f, 3.f, 3.f};

#define ROWS_PER_BLOCK 8
#define NTHREADS 256

// group index of leaf i = number of group boundaries <= i (no literal table)
__device__ __forceinline__ int leaf_group(int i) {
    return (i >= 7) + (i >= 30) + (i >= 48) + (i >= 53) +
           (i >= 58) + (i >= 59) + (i >= 62);
}

__global__ __launch_bounds__(NTHREADS)
void molemap_kernel(const float* __restrict__ x,
                    float* __restrict__ out_path,
                    float* __restrict__ out_node)
{
    __shared__ __align__(16) float sx[ROWS_PER_BLOCK * 65];     // input, overwritten with path probs
    __shared__ __align__(16) float snode[ROWS_PER_BLOCK * 76];  // node_probs rows
    __shared__ float sgmax[ROWS_PER_BLOCK][8];
    __shared__ float sgrcp[ROWS_PER_BLOCK][8];
    __shared__ float sgmean[ROWS_PER_BLOCK][8];
    __shared__ float spl2[ROWS_PER_BLOCK][8];
    __shared__ float spt[ROWS_PER_BLOCK][2];

    const int tid = threadIdx.x;
    const long long row0 = (long long)blockIdx.x * ROWS_PER_BLOCK;

    // cooperative vectorized load: 8*65 = 520 floats = 130 float4
    // (block byte offset = blockIdx * 2080, 16B-aligned)
    {
        const float4* in4 = reinterpret_cast<const float4*>(x + row0 * 65);
        float4* s4 = reinterpret_cast<float4*>(sx);
        if (tid < 130) s4[tid] = in4[tid];
    }
    __syncthreads();

    const int w    = tid >> 5;   // warp = row within block
    const int lane = tid & 31;
    const float* rx = sx + w * 65;

    // per-group stats: lanes 0..7 each own one sibling group
    if (lane < 8) {
        const int a = c_ga[lane], b = c_gb[lane];
        float m = -3.402823466e38f;
        float sum = 0.f;
        for (int i = a; i < b; ++i) {
            float v = rx[i];
            sum += v;
            m = fmaxf(m, v);
        }
        float se = 0.f;
        for (int i = a; i < b; ++i) se += __expf(rx[i] - m);
        sgmax[w][lane]  = m;
        sgrcp[w][lane]  = 1.0f / se;
        sgmean[w][lane] = sum / c_gsz[lane];
    }
    __syncwarp();

    // lane 0: two level-2 softmax-of-4 and top softmax-of-2
    if (lane == 0) {
        float mean[8];
        #pragma unroll
        for (int g = 0; g < 8; ++g) mean[g] = sgmean[w][g];

        float mx0 = fmaxf(fmaxf(mean[0], mean[1]), fmaxf(mean[2], mean[3]));
        float e0 = __expf(mean[0] - mx0), e1 = __expf(mean[1] - mx0);
        float e2 = __expf(mean[2] - mx0), e3 = __expf(mean[3] - mx0);
        float rs0 = 1.0f / (e0 + e1 + e2 + e3);
        spl2[w][0] = e0 * rs0; spl2[w][1] = e1 * rs0;
        spl2[w][2] = e2 * rs0; spl2[w][3] = e3 * rs0;

        float mx1 = fmaxf(fmaxf(mean[4], mean[5]), fmaxf(mean[6], mean[7]));
        float f0 = __expf(mean[4] - mx1), f1 = __expf(mean[5] - mx1);
        float f2 = __expf(mean[6] - mx1), f3 = __expf(mean[7] - mx1);
        float rs1 = 1.0f / (f0 + f1 + f2 + f3);
        spl2[w][4] = f0 * rs1; spl2[w][5] = f1 * rs1;
        spl2[w][6] = f2 * rs1; spl2[w][7] = f3 * rs1;

        // exact recombination of group means into the two top-level means
        float s53 = mean[0]*7.f + mean[1]*23.f + mean[2]*18.f + mean[3]*5.f;
        float s12 = mean[4]*5.f + mean[5]*1.f + mean[6]*3.f + mean[7]*3.f;
        float m0 = s53 * (1.0f / 53.0f);
        float m1 = s12 * (1.0f / 12.0f);
        float mxt = fmaxf(m0, m1);
        float t0 = __expf(m0 - mxt), t1 = __expf(m1 - mxt);
        float rst = 1.0f / (t0 + t1);
        spt[w][0] = t0 * rst;
        spt[w][1] = t1 * rst;
    }
    __syncwarp();

    // per-leaf: leaf prob -> node region, path prob -> path region (in-place over sx)
    for (int idx = lane; idx < 65; idx += 32) {
        int g = leaf_group(idx);
        float lp = __expf(rx[idx] - sgmax[w][g]) * sgrcp[w][g];
        snode[w * 76 + idx] = lp;                                 // node_probs[0..64]
        sx[w * 65 + idx] = lp * spl2[w][g] * spt[w][idx >= 53];   // leaf_path_probs
    }
    if (lane < 8) snode[w * 76 + 65 + lane] = spl2[w][lane];      // node_probs[65..72]
    if (lane < 2) snode[w * 76 + 73 + lane] = spt[w][lane];       // node_probs[73..74]
    if (lane == 0) snode[w * 76 + 75] = 1.0f;                     // root

    __syncthreads();

    // coalesced vectorized stores
    {
        // path: 130 float4/block, block byte offset = blockIdx*2080 (16B-aligned)
        float4* op4 = reinterpret_cast<float4*>(out_path + row0 * 65);
        const float4* sp4 = reinterpret_cast<const float4*>(sx);
        if (tid < 130) op4[tid] = sp4[tid];

        // node: 152 float4/block; base offset N*65*4 is 16B-divisible, block off = blockIdx*2432
        float4* on4 = reinterpret_cast<float4*>(out_node + row0 * 76);
        const float4* sn4 = reinterpret_cast<const float4*>(snode);
        if (tid < 152) on4[tid] = sn4[tid];
    }
}

extern "C" void kernel_launch(void* const* d_in, const int* in_sizes, int n_in,
                              void* d_out, int out_size)
{
    const float* x = (const float*)d_in[0];
    const long long N = (long long)in_sizes[0] / 65;   // 524288
    float* out_path = (float*)d_out;
    float* out_node = out_path + N * 65;

    const int blocks = (int)(N / ROWS_PER_BLOCK);
    molemap_kernel<<<blocks, NTHREADS>>>(x, out_path, out_node);
}

// round 4
// speedup vs baseline: 4.9507x; 4.9507x over previous
#include <cuda_runtime.h>
#include <cuda_bf16.h>

// Thread-per-row hierarchical softmax.
// Fused output layout (flat): [ leaf_path_probs (N*65) | node_probs (N*76) ]

#define ROWS 128
#define NT   128

__global__ __launch_bounds__(NT)
void molemap_kernel(const float* __restrict__ x,
                    float* __restrict__ out_path,
                    float* __restrict__ out_node)
{
    // One reused staging buffer: 128*76 = 9728 floats = 38912 B
    __shared__ __align__(16) float buf[ROWS * 76];

    const int tid = threadIdx.x;
    const long long row0 = (long long)blockIdx.x * ROWS;

    // ---- Phase A: vectorized load, 128*65 = 8320 floats = 2080 float4 ----
    {
        const float4* in4 = reinterpret_cast<const float4*>(x + row0 * 65);
        float4* b4 = reinterpret_cast<float4*>(buf);
        #pragma unroll
        for (int k = 0; k < 17; ++k) {
            int idx = tid + k * NT;
            if (idx < 2080) b4[idx] = in4[idx];
        }
    }
    __syncthreads();

    // ---- Phase B: thread-per-row compute, everything in registers ----
    float v[65];
    float* rx = buf + tid * 65;   // stride 65 ≡ 1 (mod 32): conflict-free LDS/STS
    #pragma unroll
    for (int i = 0; i < 65; ++i) v[i] = rx[i];

    float grcp[8], mean[8];

    // per-group: raw max+sum, then exp in-place and sum of exps (literal bounds -> full unroll)
#define GROUP_STATS(G, A, B, RSZ)                                   \
    {                                                               \
        float m = v[A], s = 0.f;                                    \
        _Pragma("unroll")                                           \
        for (int i = A; i < B; ++i) { s += v[i]; m = fmaxf(m, v[i]); } \
        float e = 0.f;                                              \
        _Pragma("unroll")                                           \
        for (int i = A; i < B; ++i) { v[i] = __expf(v[i] - m); e += v[i]; } \
        grcp[G] = 1.0f / e;                                         \
        mean[G] = s * (RSZ);                                        \
    }
    GROUP_STATS(0,  0,  7, 1.0f/7.0f)
    GROUP_STATS(1,  7, 30, 1.0f/23.0f)
    GROUP_STATS(2, 30, 48, 1.0f/18.0f)
    GROUP_STATS(3, 48, 53, 1.0f/5.0f)
    GROUP_STATS(4, 53, 58, 1.0f/5.0f)
    GROUP_STATS(5, 58, 59, 1.0f)
    GROUP_STATS(6, 59, 62, 1.0f/3.0f)
    GROUP_STATS(7, 62, 65, 1.0f/3.0f)
#undef GROUP_STATS

    // level-2: two softmax-of-4 over group means
    float pl2[8], pt0, pt1;
    {
        float mx0 = fmaxf(fmaxf(mean[0], mean[1]), fmaxf(mean[2], mean[3]));
        float e0 = __expf(mean[0]-mx0), e1 = __expf(mean[1]-mx0);
        float e2 = __expf(mean[2]-mx0), e3 = __expf(mean[3]-mx0);
        float r0 = 1.0f / (e0 + e1 + e2 + e3);
        pl2[0] = e0*r0; pl2[1] = e1*r0; pl2[2] = e2*r0; pl2[3] = e3*r0;

        float mx1 = fmaxf(fmaxf(mean[4], mean[5]), fmaxf(mean[6], mean[7]));
        float f0 = __expf(mean[4]-mx1), f1 = __expf(mean[5]-mx1);
        float f2 = __expf(mean[6]-mx1), f3 = __expf(mean[7]-mx1);
        float r1 = 1.0f / (f0 + f1 + f2 + f3);
        pl2[4] = f0*r1; pl2[5] = f1*r1; pl2[6] = f2*r1; pl2[7] = f3*r1;

        // top means: exact recombination of group sums (mean*size)
        float m0 = (mean[0]*7.f + mean[1]*23.f + mean[2]*18.f + mean[3]*5.f) * (1.0f/53.0f);
        float m1 = (mean[4]*5.f + mean[5]*1.f + mean[6]*3.f + mean[7]*3.f) * (1.0f/12.0f);
        float mxt = fmaxf(m0, m1);
        float t0 = __expf(m0 - mxt), t1 = __expf(m1 - mxt);
        float rt = 1.0f / (t0 + t1);
        pt0 = t0 * rt;
        pt1 = t1 * rt;
    }

    // fused path scale per group: k = (1/sumexp) * p_lvl2 * p_top
    float ks[8];
    #pragma unroll
    for (int g = 0; g < 8; ++g) ks[g] = grcp[g] * pl2[g] * (g < 4 ? pt0 : pt1);

    // write path probs in-place (own row only)
#define PATH_WRITE(G, A, B)                                   \
    _Pragma("unroll")                                         \
    for (int i = A; i < B; ++i) rx[i] = v[i] * ks[G];
    PATH_WRITE(0,  0,  7)  PATH_WRITE(1,  7, 30)
    PATH_WRITE(2, 30, 48)  PATH_WRITE(3, 48, 53)
    PATH_WRITE(4, 53, 58)  PATH_WRITE(5, 58, 59)
    PATH_WRITE(6, 59, 62)  PATH_WRITE(7, 62, 65)
#undef PATH_WRITE

    __syncthreads();

    // ---- Phase C: stream path out, 2080 float4 ----
    {
        float4* op4 = reinterpret_cast<float4*>(out_path + row0 * 65);
        const float4* b4 = reinterpret_cast<const float4*>(buf);
        #pragma unroll
        for (int k = 0; k < 17; ++k) {
            int idx = tid + k * NT;
            if (idx < 2080) op4[idx] = b4[idx];
        }
    }
    __syncthreads();   // all reads of buf done before node-layout rewrite

    // ---- Phase D: write node rows into [128][76] layout ----
    {
        float* rn = buf + tid * 76;
#define NODE_WRITE(G, A, B)                                     \
        _Pragma("unroll")                                       \
        for (int i = A; i < B; ++i) rn[i] = v[i] * grcp[G];
        NODE_WRITE(0,  0,  7)  NODE_WRITE(1,  7, 30)
        NODE_WRITE(2, 30, 48)  NODE_WRITE(3, 48, 53)
        NODE_WRITE(4, 53, 58)  NODE_WRITE(5, 58, 59)
        NODE_WRITE(6, 59, 62)  NODE_WRITE(7, 62, 65)
#undef NODE_WRITE
        #pragma unroll
        for (int g = 0; g < 8; ++g) rn[65 + g] = pl2[g];
        rn[73] = pt0;
        rn[74] = pt1;
        rn[75] = 1.0f;
    }
    __syncthreads();

    // ---- Phase E: stream node out, 128*76 = 9728 floats = 2432 float4 ----
    {
        float4* on4 = reinterpret_cast<float4*>(out_node + row0 * 76);
        const float4* b4 = reinterpret_cast<const float4*>(buf);
        #pragma unroll
        for (int k = 0; k < 19; ++k) {
            int idx = tid + k * NT;
            if (idx < 2432) on4[idx] = b4[idx];
        }
    }
}

extern "C" void kernel_launch(void* const* d_in, const int* in_sizes, int n_in,
                              void* d_out, int out_size)
{
    const float* x = (const float*)d_in[0];
    const long long N = (long long)in_sizes[0] / 65;   // 524288
    float* out_path = (float*)d_out;
    float* out_node = out_path + N * 65;

    const int blocks = (int)(N / ROWS);                // 4096
    molemap_kernel<<<blocks, NT>>>(x, out_path, out_node);
}